// round 13
// baseline (speedup 1.0000x reference)
#include <cuda_runtime.h>

// out[i] = gen_map[x_gen[i]] + c*cs[i] + d*tdp[i], N = 8388608. DRAM-bound.
// v8: warp-contiguous 128-bit reads (4 full L1 lines per wavefront, vs v6's
// 8 half-filled) + warp-shuffle exchange so each lane still owns 8 contiguous
// output elements for the fused 256-bit evict_first store (the R11 win).

#define BLOCK 256

struct U64x4 { unsigned long long a, b, c, d; };

__device__ __forceinline__ void stg_ef_256(void* p, const U64x4& v) {
    asm volatile("st.global.L2::evict_first.v4.b64 [%0], {%1,%2,%3,%4};"
        :: "l"(p), "l"(v.a), "l"(v.b), "l"(v.c), "l"(v.d) : "memory");
}
__device__ __forceinline__ unsigned long long pack64(float lo, float hi) {
    return (unsigned long long)__float_as_uint(lo)
         | ((unsigned long long)__float_as_uint(hi) << 32);
}
__device__ __forceinline__ float sel_shfl(float a, float b, int src, bool hi) {
    float va = __shfl_sync(0xffffffffu, a, src);
    float vb = __shfl_sync(0xffffffffu, b, src);
    return hi ? vb : va;
}

// Fast path: NO bounds checks (grid exactly covers n4 float4-units, n4 % 512 == 0).
__global__ void __launch_bounds__(BLOCK) fused_gather_axpy_v8(
    const int4* __restrict__ x_gen4,
    const float4* __restrict__ cs4,
    const float4* __restrict__ tdp4,
    const float* __restrict__ gen_map,
    const float* __restrict__ c_p,
    const float* __restrict__ d_p,
    float* __restrict__ out)
{
    __shared__ float s_map[1024];
    ((float4*)s_map)[threadIdx.x] = __ldg(&((const float4*)gen_map)[threadIdx.x]);

    const float c = __ldg(c_p);
    const float d = __ldg(d_p);

    const int lane = threadIdx.x & 31;
    const int warp = threadIdx.x >> 5;
    // Each warp owns 64 consecutive float4-units (1024 B per array).
    const long long warp_base = ((long long)blockIdx.x * BLOCK + warp * 32) * 2;

    // Warp-contiguous loads: lanes 0..31 cover 512 contiguous bytes per instr.
    const long long uA = warp_base + lane;
    const long long uB = warp_base + 32 + lane;
    int4   gA = __ldcg(&x_gen4[uA]);
    int4   gB = __ldcg(&x_gen4[uB]);
    float4 sA = __ldcg(&cs4[uA]);
    float4 sB = __ldcg(&cs4[uB]);
    float4 tA = __ldcg(&tdp4[uA]);
    float4 tB = __ldcg(&tdp4[uB]);

    __syncthreads();

    float4 rA, rB;
    rA.x = s_map[gA.x] + c * sA.x + d * tA.x;
    rA.y = s_map[gA.y] + c * sA.y + d * tA.y;
    rA.z = s_map[gA.z] + c * sA.z + d * tA.z;
    rA.w = s_map[gA.w] + c * sA.w + d * tA.w;
    rB.x = s_map[gB.x] + c * sB.x + d * tB.x;
    rB.y = s_map[gB.y] + c * sB.y + d * tB.y;
    rB.z = s_map[gB.z] + c * sB.z + d * tB.z;
    rB.w = s_map[gB.w] + c * sB.w + d * tB.w;

    // Exchange: lane l must store output units (warp_base + 2l) and (+2l+1).
    // Unit u (0..63 within warp) lives in lane (u & 31), slot A if u < 32 else B.
    const int  s0 = (2 * lane) & 31;
    const int  s1 = (2 * lane + 1) & 31;
    const bool hi = lane >= 16;   // upper half needs slot-B values

    float o0 = sel_shfl(rA.x, rB.x, s0, hi);
    float o1 = sel_shfl(rA.y, rB.y, s0, hi);
    float o2 = sel_shfl(rA.z, rB.z, s0, hi);
    float o3 = sel_shfl(rA.w, rB.w, s0, hi);
    float o4 = sel_shfl(rA.x, rB.x, s1, hi);
    float o5 = sel_shfl(rA.y, rB.y, s1, hi);
    float o6 = sel_shfl(rA.z, rB.z, s1, hi);
    float o7 = sel_shfl(rA.w, rB.w, s1, hi);

    U64x4 o;
    o.a = pack64(o0, o1);
    o.b = pack64(o2, o3);
    o.c = pack64(o4, o5);
    o.d = pack64(o6, o7);
    // Lane l's 8 elems start at float index (warp_base + 2*lane) * 4.
    stg_ef_256(out + (warp_base + 2 * lane) * 4, o);
}

// Generic fallback (any N), element-granular.
__global__ void fused_gather_axpy_generic(
    const int* __restrict__ x_gen,
    const float* __restrict__ cs,
    const float* __restrict__ tdp,
    const float* __restrict__ gen_map,
    const float* __restrict__ c_p,
    const float* __restrict__ d_p,
    float* __restrict__ out,
    int n)
{
    int i = blockIdx.x * blockDim.x + threadIdx.x;
    if (i >= n) return;
    float c = __ldg(c_p);
    float d = __ldg(d_p);
    out[i] = __ldg(&gen_map[x_gen[i]]) + c * cs[i] + d * tdp[i];
}

extern "C" void kernel_launch(void* const* d_in, const int* in_sizes, int n_in,
                              void* d_out, int out_size)
{
    const int*   x_gen   = (const int*)d_in[0];
    // d_in[1] = x_ix (unused)
    const float* cs      = (const float*)d_in[2];
    const float* tdp     = (const float*)d_in[3];
    const float* gen_map = (const float*)d_in[4];
    // d_in[5] = b (unused)
    const float* c_p     = (const float*)d_in[6];
    const float* d_p     = (const float*)d_in[7];
    float* out = (float*)d_out;

    const int n  = in_sizes[0];
    const int n4 = n / 4;
    const int units_per_block = BLOCK * 2;

    if ((n % 4 == 0) && (n4 % units_per_block == 0)) {
        // Exact-cover fast path (holds for N = 8388608: 4096 blocks).
        fused_gather_axpy_v8<<<n4 / units_per_block, BLOCK>>>(
            (const int4*)x_gen, (const float4*)cs, (const float4*)tdp,
            gen_map, c_p, d_p, out);
    } else {
        fused_gather_axpy_generic<<<(n + 255) / 256, 256>>>(
            x_gen, cs, tdp, gen_map, c_p, d_p, out, n);
    }
}